// round 2
// baseline (speedup 1.0000x reference)
#include <cuda_runtime.h>
#include <math.h>

#define B 512
#define S 256
#define H 256
#define U 10
#define G4 1024   // 4*H

// ---------------- device scratch (static allocations only) ----------------
__device__ float g_enc_out[B * S * H];   // [b][s][h]  134 MB
__device__ float g_encW1[B * U * S];     // [b][u][s]  5 MB
__device__ float g_Wenc[257 * G4];       // interleaved gate cols
__device__ float g_Wdec[513 * G4];
__device__ float g_bias_enc[G4];
__device__ float g_bias_dec[G4];
__device__ float g_hA[B * H];
__device__ float g_hB[B * H];
__device__ float g_c[B * H];
__device__ float g_ext[B * 257];         // decoder lstm extra input: [di(256) | dec_in(1)]
__device__ float g_decnext[B];           // staged teacher-forced input
__device__ float g_lossbuf[S * B];
__device__ int   g_y64;

// ---------------- precise, fast-math-immune transcendentals ----------------
// expf replacement: Cephes-style, all fmaf (never contracted away), ~1-2 ulp.
__device__ __forceinline__ float exp_p(float x)
{
    x = fminf(fmaxf(x, -87.0f), 87.0f);
    float t = fmaf(x, 1.44269504088896341f, 12582912.0f);  // rint via magic number
    float n = t - 12582912.0f;
    float r = fmaf(n, -0.693359375f, x);
    r = fmaf(n, 2.12194440e-4f, r);
    float p = 1.9875691500e-4f;
    p = fmaf(p, r, 1.3981999507e-3f);
    p = fmaf(p, r, 8.3334519073e-3f);
    p = fmaf(p, r, 4.1665795894e-2f);
    p = fmaf(p, r, 1.6666665459e-1f);
    p = fmaf(p, r, 5.0000001201e-1f);
    float res = fmaf(r * r, p, r) + 1.0f;
    int i = (int)n;
    float scale = __int_as_float((i + 127) << 23);
    return res * scale;
}

__device__ __forceinline__ float sig_p(float v)
{
    if (v >= 0.0f) {
        float e = exp_p(-v);
        return __fdiv_rn(1.0f, 1.0f + e);
    } else {
        float e = exp_p(v);
        return __fdiv_rn(e, 1.0f + e);
    }
}

__device__ __forceinline__ float tanh_p(float x)
{
    float a = fabsf(x);
    float res;
    if (a < 0.625f) {
        float z = x * x;
        float p = -8.24464904201e-3f;
        p = fmaf(p, z, 2.06390887954e-2f);
        p = fmaf(p, z, -5.37397155531e-2f);
        p = fmaf(p, z, 1.33314422036e-1f);
        p = fmaf(p, z, -3.33332819422e-1f);
        res = fmaf(p * z, x, x);
        return res;
    }
    if (a > 9.0f) {
        res = 1.0f;
    } else {
        float e = exp_p(2.0f * a);
        res = 1.0f - __fdiv_rn(2.0f, e + 1.0f);
    }
    return (x < 0.0f) ? -res : res;
}

// Kahan step
#define KAHAN_ADD(acc, comp, val)            \
    do {                                     \
        float _y = (val) - (comp);           \
        float _t = (acc) + _y;               \
        (comp) = (_t - (acc)) - _y;          \
        (acc) = _t;                          \
    } while (0)

// ---------------- weight prep: interleave gate columns --------------------
// new col j = 4*h + g  maps to original row r = g*256 + h (PyTorch i,f,g,o order)
__global__ void prep_kernel(const float* __restrict__ eWih, const float* __restrict__ eWhh,
                            const float* __restrict__ ebih, const float* __restrict__ ebhh,
                            const float* __restrict__ dWih, const float* __restrict__ dWhh,
                            const float* __restrict__ dbih, const float* __restrict__ dbhh)
{
    int idx = blockIdx.x * blockDim.x + threadIdx.x;
    if (idx >= 513 * G4) return;
    int k = idx >> 10, j = idx & 1023;
    int h = j >> 2, g = j & 3;
    int r = g * 256 + h;
    float wd = (k < 256) ? dWhh[r * 256 + k] : dWih[r * 257 + (k - 256)];
    g_Wdec[idx] = wd;
    if (k < 257) {
        float we = (k < 256) ? eWhh[r * 256 + k] : eWih[r];
        g_Wenc[idx] = we;
    }
    if (k == 0) {
        g_bias_enc[j] = ebih[r] + ebhh[r];
        g_bias_dec[j] = dbih[r] + dbhh[r];
    }
}

__global__ void init_kernel()
{
    int idx = blockIdx.x * blockDim.x + threadIdx.x;
    if (idx < B * H) { g_hA[idx] = 0.f; g_c[idx] = 0.f; }
    if (idx < B)     { g_decnext[idx] = 0.f; }
}

// y dtype probe: if int64, odd int32 words (high halves) are all zero.
__global__ void detect_y(const void* __restrict__ y)
{
    const int* yi = (const int*)y;
    int all0 = 1;
    for (int i = 1; i < 64; i += 2) if (yi[i] != 0) all0 = 0;
    g_y64 = all0;
}

// ---------------- fused GEMM + LSTM pointwise step -------------------------
// gates[b][j] = sum_k A[b][k] * W[k][j] + bias[j],  A = [h | ext]
// Kahan-compensated accumulation for recurrence-grade accuracy.
__global__ __launch_bounds__(256) void lstm_step(const float* __restrict__ xptr,
                                                 int K, int is_enc, int t, int parity)
{
    const float* h_in  = parity ? g_hB : g_hA;
    float*       h_out = parity ? g_hA : g_hB;
    const float* W     = is_enc ? g_Wenc : g_Wdec;
    const float* bias  = is_enc ? g_bias_enc : g_bias_dec;
    const float* ext;  int estride;
    if (is_enc) { ext = xptr + t; estride = S;   }   // ext col 0 = x[b][t]
    else        { ext = g_ext;    estride = 257; }

    __shared__ float As[64][65];   // [row][k]
    __shared__ float Ws[64][64];   // [k][j]

    int rb = blockIdx.y * 64, jc = blockIdx.x * 64;
    int tid = threadIdx.x;
    int tx = tid & 15, ty = tid >> 4;

    float acc[4][4] = {};
    float cmp[4][4] = {};

    for (int kc = 0; kc < K; kc += 64) {
        #pragma unroll
        for (int l = 0; l < 16; l++) {
            int idx = tid + l * 256;
            int r = idx >> 6, k = idx & 63;
            int kg = kc + k;
            float v;
            if (kg < 256)      v = h_in[(rb + r) * 256 + kg];
            else if (kg < K)   v = ext[(rb + r) * estride + (kg - 256)];
            else               v = 0.f;
            As[r][k] = v;
        }
        #pragma unroll
        for (int l = 0; l < 16; l++) {
            int idx = tid + l * 256;
            int k = idx >> 6, j = idx & 63;
            int kg = kc + k;
            Ws[k][j] = (kg < K) ? W[kg * G4 + jc + j] : 0.f;
        }
        __syncthreads();
        #pragma unroll
        for (int k = 0; k < 64; k++) {
            float4 w = *(const float4*)&Ws[k][tx * 4];
            float a0 = As[ty * 4 + 0][k];
            float a1 = As[ty * 4 + 1][k];
            float a2 = As[ty * 4 + 2][k];
            float a3 = As[ty * 4 + 3][k];
            KAHAN_ADD(acc[0][0], cmp[0][0], a0 * w.x);
            KAHAN_ADD(acc[0][1], cmp[0][1], a0 * w.y);
            KAHAN_ADD(acc[0][2], cmp[0][2], a0 * w.z);
            KAHAN_ADD(acc[0][3], cmp[0][3], a0 * w.w);
            KAHAN_ADD(acc[1][0], cmp[1][0], a1 * w.x);
            KAHAN_ADD(acc[1][1], cmp[1][1], a1 * w.y);
            KAHAN_ADD(acc[1][2], cmp[1][2], a1 * w.z);
            KAHAN_ADD(acc[1][3], cmp[1][3], a1 * w.w);
            KAHAN_ADD(acc[2][0], cmp[2][0], a2 * w.x);
            KAHAN_ADD(acc[2][1], cmp[2][1], a2 * w.y);
            KAHAN_ADD(acc[2][2], cmp[2][2], a2 * w.z);
            KAHAN_ADD(acc[2][3], cmp[2][3], a2 * w.w);
            KAHAN_ADD(acc[3][0], cmp[3][0], a3 * w.x);
            KAHAN_ADD(acc[3][1], cmp[3][1], a3 * w.y);
            KAHAN_ADD(acc[3][2], cmp[3][2], a3 * w.z);
            KAHAN_ADD(acc[3][3], cmp[3][3], a3 * w.w);
        }
        __syncthreads();
    }

    int unit = (jc >> 2) + tx;              // hidden unit index 0..255
    int jb = jc + tx * 4;
    float bi = bias[jb + 0], bf = bias[jb + 1], bg = bias[jb + 2], bo = bias[jb + 3];
    #pragma unroll
    for (int r = 0; r < 4; r++) {
        int b = rb + ty * 4 + r;
        float iv = sig_p(acc[r][0] + bi);
        float fv = sig_p(acc[r][1] + bf);
        float gv = tanh_p(acc[r][2] + bg);
        float ov = sig_p(acc[r][3] + bo);
        float cold = g_c[b * H + unit];
        float cn = fv * cold + iv * gv;
        float hh = ov * tanh_p(cn);
        g_c[b * H + unit] = cn;
        h_out[b * H + unit] = hh;
        if (is_enc) g_enc_out[b * (S * H) + t * H + unit] = hh;
    }
}

// ---------------- encW1 precompute: [b][u][s] = enc_out[b,s,:] . W1[u,:] ----
__global__ __launch_bounds__(256) void encW1_kernel(const float* __restrict__ W1)
{
    int w = blockIdx.x * 8 + (threadIdx.x >> 5);
    int lane = threadIdx.x & 31;
    int b = w >> 8, s = w & 255;
    const float* e = g_enc_out + b * (S * H) + s * H;
    float ev[8];
    #pragma unroll
    for (int i = 0; i < 8; i++) ev[i] = e[lane + 32 * i];
    #pragma unroll
    for (int u = 0; u < U; u++) {
        float p = 0.f, c = 0.f;
        #pragma unroll
        for (int i = 0; i < 8; i++) KAHAN_ADD(p, c, ev[i] * W1[u * 256 + lane + 32 * i]);
        #pragma unroll
        for (int o = 16; o; o >>= 1) p += __shfl_xor_sync(0xffffffffu, p, o);
        if (lane == 0) g_encW1[b * (U * S) + u * S + s] = p;
    }
}

// ---------------- fused attention step: logits/softmax/argmax/loss/di ------
__global__ __launch_bounds__(256) void attn_step(const float* __restrict__ x,
                                                 const void* __restrict__ yv,
                                                 const float* __restrict__ W2,
                                                 const float* __restrict__ V,
                                                 float* __restrict__ outp,
                                                 int t, int parity)
{
    const float* h_in = parity ? g_hB : g_hA;
    int b = blockIdx.x, tid = threadIdx.x;

    __shared__ float sh_h[256];
    __shared__ float sh_w2h[16];
    __shared__ float sV[16];
    __shared__ float sh_log[256];
    __shared__ float sh_aj[256];
    __shared__ float sh_red[256];
    __shared__ int   sh_idx[256];

    sh_h[tid] = h_in[b * H + tid];
    if (tid == 0) g_ext[b * 257 + 256] = g_decnext[b];   // dec_in for THIS step
    if (tid < U)  sV[tid] = V[tid];
    __syncthreads();

    int wid = tid >> 5, lane = tid & 31;
    for (int u = wid; u < U; u += 8) {
        float p = 0.f, c = 0.f;
        #pragma unroll
        for (int k = lane; k < 256; k += 32) KAHAN_ADD(p, c, sh_h[k] * W2[u * 256 + k]);
        #pragma unroll
        for (int o = 16; o; o >>= 1) p += __shfl_xor_sync(0xffffffffu, p, o);
        if (lane == 0) sh_w2h[u] = p;
    }
    __syncthreads();

    const float* ew = g_encW1 + b * (U * S) + tid;
    float lg = 0.f, lgc = 0.f;
    #pragma unroll
    for (int u = 0; u < U; u++)
        KAHAN_ADD(lg, lgc, sV[u] * tanh_p(ew[u * S] + sh_w2h[u]));
    sh_log[tid] = lg;
    sh_red[tid] = lg;
    sh_idx[tid] = tid;
    __syncthreads();

    // argmax (first occurrence on ties, matching jnp.argmax)
    #pragma unroll
    for (int off = 128; off; off >>= 1) {
        if (tid < off) {
            float ov = sh_red[tid + off]; int oi = sh_idx[tid + off];
            float cv = sh_red[tid];       int ci = sh_idx[tid];
            if (ov > cv || (ov == cv && oi < ci)) { sh_red[tid] = ov; sh_idx[tid] = oi; }
        }
        __syncthreads();
    }
    float mx = sh_red[0]; int mi = sh_idx[0];
    __syncthreads();

    float p = exp_p(lg - mx);
    sh_red[tid] = p;
    __syncthreads();
    #pragma unroll
    for (int off = 128; off; off >>= 1) {
        if (tid < off) sh_red[tid] += sh_red[tid + off];
        __syncthreads();
    }
    float sum = sh_red[0];
    sh_aj[tid] = __fdiv_rn(p, sum);

    if (tid == 0) {
        int yi = g_y64 ? (int)((const long long*)yv)[b * S + t]
                       : ((const int*)yv)[b * S + t];
        float logpy = sh_log[yi] - mx - (float)log((double)sum);
        g_lossbuf[t * B + b] = -logpy;
        outp[t * B + b] = (float)mi;
        g_decnext[b] = x[b * S + yi];    // teacher force for NEXT step
    }
    __syncthreads();

    // di[b][tid] = sum_s aj[s] * enc_out[b][s][tid]   (feeds the recurrence)
    const float* eb = g_enc_out + b * (S * H) + tid;
    float acc = 0.f, accc = 0.f;
    #pragma unroll 4
    for (int s2 = 0; s2 < 256; s2++) KAHAN_ADD(acc, accc, sh_aj[s2] * eb[s2 * H]);
    g_ext[b * 257 + tid] = acc;
}

// ---------------- deterministic loss reduction ------------------------------
__global__ void loss_reduce(float* __restrict__ outp, int do_write)
{
    __shared__ float sr[256];
    int tid = threadIdx.x;
    float a = 0.f, c = 0.f;
    for (int i = tid; i < S * B; i += 256) KAHAN_ADD(a, c, g_lossbuf[i]);
    sr[tid] = a;
    __syncthreads();
    #pragma unroll
    for (int off = 128; off; off >>= 1) {
        if (tid < off) sr[tid] += sr[tid + off];
        __syncthreads();
    }
    if (tid == 0 && do_write) outp[S * B] = __fdiv_rn(sr[0], 512.f * 512.f);
}

// ---------------- host launch ----------------------------------------------
extern "C" void kernel_launch(void* const* d_in, const int* in_sizes, int n_in,
                              void* d_out, int out_size)
{
    const float* x    = (const float*)d_in[0];
    const void*  y    = d_in[1];
    const float* eWih = (const float*)d_in[2];
    const float* eWhh = (const float*)d_in[3];
    const float* ebih = (const float*)d_in[4];
    const float* ebhh = (const float*)d_in[5];
    const float* dWih = (const float*)d_in[6];
    const float* dWhh = (const float*)d_in[7];
    const float* dbih = (const float*)d_in[8];
    const float* dbhh = (const float*)d_in[9];
    const float* W1   = (const float*)d_in[10];
    const float* W2   = (const float*)d_in[11];
    const float* V    = (const float*)d_in[12];
    float* outp = (float*)d_out;

    prep_kernel<<<(513 * G4 + 255) / 256, 256>>>(eWih, eWhh, ebih, ebhh,
                                                 dWih, dWhh, dbih, dbhh);
    init_kernel<<<(B * H + 255) / 256, 256>>>();
    detect_y<<<1, 1>>>(y);

    dim3 grid(G4 / 64, B / 64);   // 16 x 8

    // encoder
    for (int t = 0; t < S; t++)
        lstm_step<<<grid, 256>>>(x, 257, 1, t, t & 1);

    encW1_kernel<<<B * S / 8, 256>>>(W1);

    // decoder
    for (int t = 0; t < S; t++) {
        attn_step<<<B, 256>>>(x, y, W2, V, outp, t, t & 1);
        lstm_step<<<grid, 256>>>(x, 513, 0, t, t & 1);
    }

    loss_reduce<<<1, 256>>>(outp, out_size > S * B ? 1 : 0);
}

// round 3
// speedup vs baseline: 1.6367x; 1.6367x over previous
#include <cuda_runtime.h>
#include <math.h>

#define B 512
#define S 256
#define H 256
#define U 10
#define G4 1024   // 4*H

// ---------------- device scratch (static allocations only) ----------------
__device__ float g_enc_out[B * S * H];   // [b][s][h]  134 MB
__device__ float g_encW1[B * U * S];     // [b][u][s]  5 MB
__device__ float g_Wenc[257 * G4];       // interleaved gate cols
__device__ float g_Wdec[513 * G4];
__device__ float g_bias_enc[G4];
__device__ float g_bias_dec[G4];
__device__ float g_hA[B * H];
__device__ float g_hB[B * H];
__device__ float g_c[B * H];
__device__ float g_ext[B * 257];         // decoder lstm extra input: [di(256) | dec_in(1)]
__device__ float g_decnext[B];           // staged teacher-forced input
__device__ float g_lossbuf[S * B];
__device__ int   g_y64;

// ---------------- precise, fast-math-immune transcendentals ----------------
__device__ __forceinline__ float exp_p(float x)
{
    x = fminf(fmaxf(x, -87.0f), 87.0f);
    float t = fmaf(x, 1.44269504088896341f, 12582912.0f);  // rint via magic number
    float n = t - 12582912.0f;
    float r = fmaf(n, -0.693359375f, x);
    r = fmaf(n, 2.12194440e-4f, r);
    float p = 1.9875691500e-4f;
    p = fmaf(p, r, 1.3981999507e-3f);
    p = fmaf(p, r, 8.3334519073e-3f);
    p = fmaf(p, r, 4.1665795894e-2f);
    p = fmaf(p, r, 1.6666665459e-1f);
    p = fmaf(p, r, 5.0000001201e-1f);
    float res = fmaf(r * r, p, r) + 1.0f;
    int i = (int)n;
    float scale = __int_as_float((i + 127) << 23);
    return res * scale;
}

__device__ __forceinline__ float sig_p(float v)
{
    if (v >= 0.0f) {
        float e = exp_p(-v);
        return __fdiv_rn(1.0f, 1.0f + e);
    } else {
        float e = exp_p(v);
        return __fdiv_rn(e, 1.0f + e);
    }
}

__device__ __forceinline__ float tanh_p(float x)
{
    float a = fabsf(x);
    float res;
    if (a < 0.625f) {
        float z = x * x;
        float p = -8.24464904201e-3f;
        p = fmaf(p, z, 2.06390887954e-2f);
        p = fmaf(p, z, -5.37397155531e-2f);
        p = fmaf(p, z, 1.33314422036e-1f);
        p = fmaf(p, z, -3.33332819422e-1f);
        res = fmaf(p * z, x, x);
        return res;
    }
    if (a > 9.0f) {
        res = 1.0f;
    } else {
        float e = exp_p(2.0f * a);
        res = 1.0f - __fdiv_rn(2.0f, e + 1.0f);
    }
    return (x < 0.0f) ? -res : res;
}

// Kahan step
#define KAHAN_ADD(acc, comp, val)            \
    do {                                     \
        float _y = (val) - (comp);           \
        float _t = (acc) + _y;               \
        (comp) = (_t - (acc)) - _y;          \
        (acc) = _t;                          \
    } while (0)

// ---------------- weight prep: interleave gate columns --------------------
// new col j = 4*h + g  maps to original row r = g*256 + h (PyTorch i,f,g,o order)
__global__ void prep_kernel(const float* __restrict__ eWih, const float* __restrict__ eWhh,
                            const float* __restrict__ ebih, const float* __restrict__ ebhh,
                            const float* __restrict__ dWih, const float* __restrict__ dWhh,
                            const float* __restrict__ dbih, const float* __restrict__ dbhh)
{
    int idx = blockIdx.x * blockDim.x + threadIdx.x;
    if (idx >= 513 * G4) return;
    int k = idx >> 10, j = idx & 1023;
    int h = j >> 2, g = j & 3;
    int r = g * 256 + h;
    float wd = (k < 256) ? dWhh[r * 256 + k] : dWih[r * 257 + (k - 256)];
    g_Wdec[idx] = wd;
    if (k < 257) {
        float we = (k < 256) ? eWhh[r * 256 + k] : eWih[r];
        g_Wenc[idx] = we;
    }
    if (k == 0) {
        g_bias_enc[j] = ebih[r] + ebhh[r];
        g_bias_dec[j] = dbih[r] + dbhh[r];
    }
}

__global__ void init_kernel()
{
    int idx = blockIdx.x * blockDim.x + threadIdx.x;
    if (idx < B * H) { g_hA[idx] = 0.f; g_c[idx] = 0.f; }
    if (idx < B)     { g_decnext[idx] = 0.f; }
}

// y dtype probe: if int64, odd int32 words (high halves) are all zero.
__global__ void detect_y(const void* __restrict__ y)
{
    const int* yi = (const int*)y;
    int all0 = 1;
    for (int i = 1; i < 64; i += 2) if (yi[i] != 0) all0 = 0;
    g_y64 = all0;
}

// ---------------- fused GEMM + LSTM pointwise step -------------------------
// gates[b][j] = sum_k A[b][k] * W[k][j] + bias[j],  A = [h | ext]
// Chunked-compensated accumulation: 8-term FFMA temps + Kahan fold
// (near-exact summation at ~1/3 the fma-pipe instructions of full Kahan).
__global__ __launch_bounds__(256) void lstm_step(const float* __restrict__ xptr,
                                                 int K, int is_enc, int t, int parity)
{
    const float* h_in  = parity ? g_hB : g_hA;
    float*       h_out = parity ? g_hA : g_hB;
    const float* W     = is_enc ? g_Wenc : g_Wdec;
    const float* bias  = is_enc ? g_bias_enc : g_bias_dec;
    const float* ext;  int estride;
    if (is_enc) { ext = xptr + t; estride = S;   }   // ext col 0 = x[b][t]
    else        { ext = g_ext;    estride = 257; }

    __shared__ float As[64][68];   // row stride 68 floats = 16B aligned
    __shared__ float Ws[64][64];

    int rb = blockIdx.y * 64, jc = blockIdx.x * 64;
    int tid = threadIdx.x;
    int tx = tid & 15, ty = tid >> 4;

    float acc[4][4] = {};
    float cmp[4][4] = {};

    for (int kc = 0; kc < K; kc += 64) {
        // ---- load A tile ----
        if (kc + 64 <= 256) {
            // pure h region: vectorized
            #pragma unroll
            for (int l = 0; l < 4; l++) {
                int idx = tid + l * 256;        // 0..1023 = 64 rows x 16 float4
                int r = idx >> 4, q = idx & 15;
                float4 v = *(const float4*)&h_in[(rb + r) * 256 + kc + q * 4];
                *(float4*)&As[r][q * 4] = v;
            }
        } else {
            #pragma unroll
            for (int l = 0; l < 16; l++) {
                int idx = tid + l * 256;
                int r = idx >> 6, k = idx & 63;
                int kg = kc + k;
                float v;
                if (kg < 256)      v = h_in[(rb + r) * 256 + kg];
                else if (kg < K)   v = ext[(rb + r) * estride + (kg - 256)];
                else               v = 0.f;
                As[r][k] = v;
            }
        }
        // ---- load W tile (vectorized, row-guarded) ----
        #pragma unroll
        for (int l = 0; l < 4; l++) {
            int idx = tid + l * 256;
            int k = idx >> 4, q = idx & 15;
            int kg = kc + k;
            float4 v;
            if (kg < K) v = *(const float4*)&W[kg * G4 + jc + q * 4];
            else        v = make_float4(0.f, 0.f, 0.f, 0.f);
            *(float4*)&Ws[k][q * 4] = v;
        }
        __syncthreads();

        // ---- compute: 8 sub-chunks of 8, temp FFMA chain + Kahan fold ----
        #pragma unroll
        for (int k8 = 0; k8 < 8; k8++) {
            float tmp[4][4] = {};
            #pragma unroll
            for (int kk = 0; kk < 8; kk++) {
                int k = k8 * 8 + kk;
                float4 w = *(const float4*)&Ws[k][tx * 4];
                float a0 = As[ty * 4 + 0][k];
                float a1 = As[ty * 4 + 1][k];
                float a2 = As[ty * 4 + 2][k];
                float a3 = As[ty * 4 + 3][k];
                tmp[0][0] = fmaf(a0, w.x, tmp[0][0]);
                tmp[0][1] = fmaf(a0, w.y, tmp[0][1]);
                tmp[0][2] = fmaf(a0, w.z, tmp[0][2]);
                tmp[0][3] = fmaf(a0, w.w, tmp[0][3]);
                tmp[1][0] = fmaf(a1, w.x, tmp[1][0]);
                tmp[1][1] = fmaf(a1, w.y, tmp[1][1]);
                tmp[1][2] = fmaf(a1, w.z, tmp[1][2]);
                tmp[1][3] = fmaf(a1, w.w, tmp[1][3]);
                tmp[2][0] = fmaf(a2, w.x, tmp[2][0]);
                tmp[2][1] = fmaf(a2, w.y, tmp[2][1]);
                tmp[2][2] = fmaf(a2, w.z, tmp[2][2]);
                tmp[2][3] = fmaf(a2, w.w, tmp[2][3]);
                tmp[3][0] = fmaf(a3, w.x, tmp[3][0]);
                tmp[3][1] = fmaf(a3, w.y, tmp[3][1]);
                tmp[3][2] = fmaf(a3, w.z, tmp[3][2]);
                tmp[3][3] = fmaf(a3, w.w, tmp[3][3]);
            }
            #pragma unroll
            for (int r = 0; r < 4; r++)
                #pragma unroll
                for (int cq = 0; cq < 4; cq++)
                    KAHAN_ADD(acc[r][cq], cmp[r][cq], tmp[r][cq]);
        }
        __syncthreads();
    }

    int unit = (jc >> 2) + tx;              // hidden unit index 0..255
    int jb = jc + tx * 4;
    float bi = bias[jb + 0], bf = bias[jb + 1], bg = bias[jb + 2], bo = bias[jb + 3];
    #pragma unroll
    for (int r = 0; r < 4; r++) {
        int b = rb + ty * 4 + r;
        float iv = sig_p(acc[r][0] + bi);
        float fv = sig_p(acc[r][1] + bf);
        float gv = tanh_p(acc[r][2] + bg);
        float ov = sig_p(acc[r][3] + bo);
        float cold = g_c[b * H + unit];
        float cn = fv * cold + iv * gv;
        float hh = ov * tanh_p(cn);
        g_c[b * H + unit] = cn;
        h_out[b * H + unit] = hh;
        if (is_enc) g_enc_out[b * (S * H) + t * H + unit] = hh;
    }
}

// ---------------- encW1 precompute: [b][u][s] = enc_out[b,s,:] . W1[u,:] ----
__global__ __launch_bounds__(256) void encW1_kernel(const float* __restrict__ W1)
{
    int w = blockIdx.x * 8 + (threadIdx.x >> 5);
    int lane = threadIdx.x & 31;
    int b = w >> 8, s = w & 255;
    const float* e = g_enc_out + b * (S * H) + s * H;
    float ev[8];
    #pragma unroll
    for (int i = 0; i < 8; i++) ev[i] = e[lane + 32 * i];
    #pragma unroll
    for (int u = 0; u < U; u++) {
        float p = 0.f, c = 0.f;
        #pragma unroll
        for (int i = 0; i < 8; i++) KAHAN_ADD(p, c, ev[i] * W1[u * 256 + lane + 32 * i]);
        #pragma unroll
        for (int o = 16; o; o >>= 1) p += __shfl_xor_sync(0xffffffffu, p, o);
        if (lane == 0) g_encW1[b * (U * S) + u * S + s] = p;
    }
}

// ---------------- fused attention step: logits/softmax/argmax/loss/di ------
__global__ __launch_bounds__(256) void attn_step(const float* __restrict__ x,
                                                 const void* __restrict__ yv,
                                                 const float* __restrict__ W2,
                                                 const float* __restrict__ V,
                                                 float* __restrict__ outp,
                                                 int t, int parity)
{
    const float* h_in = parity ? g_hB : g_hA;
    int b = blockIdx.x, tid = threadIdx.x;

    __shared__ float sh_h[256];
    __shared__ float sh_w2h[16];
    __shared__ float sV[16];
    __shared__ float sh_log[256];
    __shared__ float sh_aj[256];
    __shared__ float sh_red[256];
    __shared__ int   sh_idx[256];

    sh_h[tid] = h_in[b * H + tid];
    if (tid == 0) g_ext[b * 257 + 256] = g_decnext[b];   // dec_in for THIS step
    if (tid < U)  sV[tid] = V[tid];
    __syncthreads();

    int wid = tid >> 5, lane = tid & 31;
    for (int u = wid; u < U; u += 8) {
        float p = 0.f, c = 0.f;
        #pragma unroll
        for (int k = lane; k < 256; k += 32) KAHAN_ADD(p, c, sh_h[k] * W2[u * 256 + k]);
        #pragma unroll
        for (int o = 16; o; o >>= 1) p += __shfl_xor_sync(0xffffffffu, p, o);
        if (lane == 0) sh_w2h[u] = p;
    }
    __syncthreads();

    const float* ew = g_encW1 + b * (U * S) + tid;
    float lg = 0.f, lgc = 0.f;
    #pragma unroll
    for (int u = 0; u < U; u++)
        KAHAN_ADD(lg, lgc, sV[u] * tanh_p(ew[u * S] + sh_w2h[u]));
    sh_log[tid] = lg;
    sh_red[tid] = lg;
    sh_idx[tid] = tid;
    __syncthreads();

    // argmax (first occurrence on ties, matching jnp.argmax)
    #pragma unroll
    for (int off = 128; off; off >>= 1) {
        if (tid < off) {
            float ov = sh_red[tid + off]; int oi = sh_idx[tid + off];
            float cv = sh_red[tid];       int ci = sh_idx[tid];
            if (ov > cv || (ov == cv && oi < ci)) { sh_red[tid] = ov; sh_idx[tid] = oi; }
        }
        __syncthreads();
    }
    float mx = sh_red[0]; int mi = sh_idx[0];
    __syncthreads();

    float p = exp_p(lg - mx);
    sh_red[tid] = p;
    __syncthreads();
    #pragma unroll
    for (int off = 128; off; off >>= 1) {
        if (tid < off) sh_red[tid] += sh_red[tid + off];
        __syncthreads();
    }
    float sum = sh_red[0];
    sh_aj[tid] = __fdiv_rn(p, sum);

    if (tid == 0) {
        int yi = g_y64 ? (int)((const long long*)yv)[b * S + t]
                       : ((const int*)yv)[b * S + t];
        float logpy = sh_log[yi] - mx - (float)log((double)sum);
        g_lossbuf[t * B + b] = -logpy;
        outp[t * B + b] = (float)mi;
        g_decnext[b] = x[b * S + yi];    // teacher force for NEXT step
    }
    __syncthreads();

    // di[b][tid] = sum_s aj[s] * enc_out[b][s][tid]   (feeds the recurrence)
    const float* eb = g_enc_out + b * (S * H) + tid;
    float acc = 0.f, accc = 0.f;
    #pragma unroll 4
    for (int s2 = 0; s2 < 256; s2++) KAHAN_ADD(acc, accc, sh_aj[s2] * eb[s2 * H]);
    g_ext[b * 257 + tid] = acc;
}

// ---------------- deterministic loss reduction ------------------------------
__global__ void loss_reduce(float* __restrict__ outp, int do_write)
{
    __shared__ float sr[256];
    int tid = threadIdx.x;
    float a = 0.f, c = 0.f;
    for (int i = tid; i < S * B; i += 256) KAHAN_ADD(a, c, g_lossbuf[i]);
    sr[tid] = a;
    __syncthreads();
    #pragma unroll
    for (int off = 128; off; off >>= 1) {
        if (tid < off) sr[tid] += sr[tid + off];
        __syncthreads();
    }
    if (tid == 0 && do_write) outp[S * B] = __fdiv_rn(sr[0], 512.f * 512.f);
}

// ---------------- host launch ----------------------------------------------
extern "C" void kernel_launch(void* const* d_in, const int* in_sizes, int n_in,
                              void* d_out, int out_size)
{
    const float* x    = (const float*)d_in[0];
    const void*  y    = d_in[1];
    const float* eWih = (const float*)d_in[2];
    const float* eWhh = (const float*)d_in[3];
    const float* ebih = (const float*)d_in[4];
    const float* ebhh = (const float*)d_in[5];
    const float* dWih = (const float*)d_in[6];
    const float* dWhh = (const float*)d_in[7];
    const float* dbih = (const float*)d_in[8];
    const float* dbhh = (const float*)d_in[9];
    const float* W1   = (const float*)d_in[10];
    const float* W2   = (const float*)d_in[11];
    const float* V    = (const float*)d_in[12];
    float* outp = (float*)d_out;

    prep_kernel<<<(513 * G4 + 255) / 256, 256>>>(eWih, eWhh, ebih, ebhh,
                                                 dWih, dWhh, dbih, dbhh);
    init_kernel<<<(B * H + 255) / 256, 256>>>();
    detect_y<<<1, 1>>>(y);

    dim3 grid(G4 / 64, B / 64);   // 16 x 8

    // encoder
    for (int t = 0; t < S; t++)
        lstm_step<<<grid, 256>>>(x, 257, 1, t, t & 1);

    encW1_kernel<<<B * S / 8, 256>>>(W1);

    // decoder
    for (int t = 0; t < S; t++) {
        attn_step<<<B, 256>>>(x, y, W2, V, outp, t, t & 1);
        lstm_step<<<grid, 256>>>(x, 513, 0, t, t & 1);
    }

    loss_reduce<<<1, 256>>>(outp, out_size > S * B ? 1 : 0);
}

// round 4
// speedup vs baseline: 2.2435x; 1.3708x over previous
#include <cuda_runtime.h>
#include <math.h>

#define B 512
#define S 256
#define H 256
#define U 10
#define G4 1024   // 4*H

// ---------------- device scratch (static allocations only) ----------------
__device__ float g_enc_out[B * S * H];   // [b][s][h]  134 MB
__device__ float g_encW1[B * U * S];     // [b][u][s]  5 MB
__device__ float g_Wenc[257 * G4];       // interleaved gate cols
__device__ float g_Wdec[513 * G4];
__device__ float g_bias_enc[G4];
__device__ float g_bias_dec[G4];
__device__ float g_hA[B * H];
__device__ float g_hB[B * H];
__device__ float g_c[B * H];
__device__ float g_ext[B * 257];         // decoder lstm extra input: [di(256) | dec_in(1)]
__device__ float g_decnext[B];           // staged teacher-forced input
__device__ float g_lossbuf[S * B];
__device__ int   g_y64;

// ---------------- precise, fast-math-immune transcendentals ----------------
__device__ __forceinline__ float exp_p(float x)
{
    x = fminf(fmaxf(x, -87.0f), 87.0f);
    float t = fmaf(x, 1.44269504088896341f, 12582912.0f);  // rint via magic number
    float n = t - 12582912.0f;
    float r = fmaf(n, -0.693359375f, x);
    r = fmaf(n, 2.12194440e-4f, r);
    float p = 1.9875691500e-4f;
    p = fmaf(p, r, 1.3981999507e-3f);
    p = fmaf(p, r, 8.3334519073e-3f);
    p = fmaf(p, r, 4.1665795894e-2f);
    p = fmaf(p, r, 1.6666665459e-1f);
    p = fmaf(p, r, 5.0000001201e-1f);
    float res = fmaf(r * r, p, r) + 1.0f;
    int i = (int)n;
    float scale = __int_as_float((i + 127) << 23);
    return res * scale;
}

__device__ __forceinline__ float sig_p(float v)
{
    if (v >= 0.0f) {
        float e = exp_p(-v);
        return __fdiv_rn(1.0f, 1.0f + e);
    } else {
        float e = exp_p(v);
        return __fdiv_rn(e, 1.0f + e);
    }
}

__device__ __forceinline__ float tanh_p(float x)
{
    float a = fabsf(x);
    float res;
    if (a < 0.625f) {
        float z = x * x;
        float p = -8.24464904201e-3f;
        p = fmaf(p, z, 2.06390887954e-2f);
        p = fmaf(p, z, -5.37397155531e-2f);
        p = fmaf(p, z, 1.33314422036e-1f);
        p = fmaf(p, z, -3.33332819422e-1f);
        res = fmaf(p * z, x, x);
        return res;
    }
    if (a > 9.0f) {
        res = 1.0f;
    } else {
        float e = exp_p(2.0f * a);
        res = 1.0f - __fdiv_rn(2.0f, e + 1.0f);
    }
    return (x < 0.0f) ? -res : res;
}

// Kahan step
#define KAHAN_ADD(acc, comp, val)            \
    do {                                     \
        float _y = (val) - (comp);           \
        float _t = (acc) + _y;               \
        (comp) = (_t - (acc)) - _y;          \
        (acc) = _t;                          \
    } while (0)

// ---------------- weight prep: interleave gate columns --------------------
// new col j = 4*h + g  maps to original row r = g*256 + h (PyTorch i,f,g,o order)
__global__ void prep_kernel(const float* __restrict__ eWih, const float* __restrict__ eWhh,
                            const float* __restrict__ ebih, const float* __restrict__ ebhh,
                            const float* __restrict__ dWih, const float* __restrict__ dWhh,
                            const float* __restrict__ dbih, const float* __restrict__ dbhh)
{
    int idx = blockIdx.x * blockDim.x + threadIdx.x;
    if (idx >= 513 * G4) return;
    int k = idx >> 10, j = idx & 1023;
    int h = j >> 2, g = j & 3;
    int r = g * 256 + h;
    float wd = (k < 256) ? dWhh[r * 256 + k] : dWih[r * 257 + (k - 256)];
    g_Wdec[idx] = wd;
    if (k < 257) {
        float we = (k < 256) ? eWhh[r * 256 + k] : eWih[r];
        g_Wenc[idx] = we;
    }
    if (k == 0) {
        g_bias_enc[j] = ebih[r] + ebhh[r];
        g_bias_dec[j] = dbih[r] + dbhh[r];
    }
}

__global__ void init_kernel()
{
    int idx = blockIdx.x * blockDim.x + threadIdx.x;
    if (idx < B * H) { g_hA[idx] = 0.f; g_c[idx] = 0.f; }
    if (idx < B)     { g_decnext[idx] = 0.f; }
}

// y dtype probe: if int64, odd int32 words (high halves) are all zero.
__global__ void detect_y(const void* __restrict__ y)
{
    const int* yi = (const int*)y;
    int all0 = 1;
    for (int i = 1; i < 64; i += 2) if (yi[i] != 0) all0 = 0;
    g_y64 = all0;
}

// ---------------- fused GEMM + LSTM pointwise step -------------------------
// gates[b][j] = sum_k A[b][k]*W[k][j] + x_extra*W[Kmain][j] + bias[j]
// 512 threads, 64x64 tile, 2x4 microtile. Chunk-8 FFMA + Kahan fold.
// KMAIN = 256 (enc) or 512 (dec); the final scalar column handled in epilogue.
__global__ __launch_bounds__(512) void lstm_step(const float* __restrict__ xptr,
                                                 int KMAIN, int is_enc, int t, int parity)
{
    const float* h_in  = parity ? g_hB : g_hA;
    float*       h_out = parity ? g_hA : g_hB;
    const float* W     = is_enc ? g_Wenc : g_Wdec;
    const float* bias  = is_enc ? g_bias_enc : g_bias_dec;

    __shared__ float As[64][68];   // row stride 68 floats
    __shared__ float Ws[64][64];

    int rb = blockIdx.y * 64, jc = blockIdx.x * 64;
    int tid = threadIdx.x;
    int tx = tid & 15, ty = tid >> 4;       // ty 0..31 -> rows ty*2, ty*2+1

    float acc[2][4] = {};
    float cmp[2][4] = {};

    for (int kc = 0; kc < KMAIN; kc += 64) {
        // ---- load A tile ----
        if (kc < 256) {
            // h region: vectorized
            #pragma unroll
            for (int l = 0; l < 2; l++) {
                int idx = tid + l * 512;        // 1024 float4 = 64 rows x 16
                int r = idx >> 4, q = idx & 15;
                float4 v = *(const float4*)&h_in[(rb + r) * 256 + kc + q * 4];
                *(float4*)&As[r][q * 4] = v;
            }
        } else {
            // decoder ext region (di): scalar loads, stride 257
            #pragma unroll
            for (int l = 0; l < 8; l++) {
                int idx = tid + l * 512;
                int r = idx >> 6, k = idx & 63;
                As[r][k] = g_ext[(rb + r) * 257 + (kc - 256 + k)];
            }
        }
        // ---- load W tile (always full rows) ----
        #pragma unroll
        for (int l = 0; l < 2; l++) {
            int idx = tid + l * 512;
            int k = idx >> 4, q = idx & 15;
            *(float4*)&Ws[k][q * 4] = *(const float4*)&W[(kc + k) * G4 + jc + q * 4];
        }
        __syncthreads();

        // ---- compute: 8 sub-chunks of 8, FFMA temp + Kahan fold ----
        #pragma unroll
        for (int k8 = 0; k8 < 8; k8++) {
            float tmp[2][4] = {};
            #pragma unroll
            for (int kk = 0; kk < 8; kk++) {
                int k = k8 * 8 + kk;
                float4 w = *(const float4*)&Ws[k][tx * 4];
                float a0 = As[ty * 2 + 0][k];
                float a1 = As[ty * 2 + 1][k];
                tmp[0][0] = fmaf(a0, w.x, tmp[0][0]);
                tmp[0][1] = fmaf(a0, w.y, tmp[0][1]);
                tmp[0][2] = fmaf(a0, w.z, tmp[0][2]);
                tmp[0][3] = fmaf(a0, w.w, tmp[0][3]);
                tmp[1][0] = fmaf(a1, w.x, tmp[1][0]);
                tmp[1][1] = fmaf(a1, w.y, tmp[1][1]);
                tmp[1][2] = fmaf(a1, w.z, tmp[1][2]);
                tmp[1][3] = fmaf(a1, w.w, tmp[1][3]);
            }
            #pragma unroll
            for (int r = 0; r < 2; r++)
                #pragma unroll
                for (int cq = 0; cq < 4; cq++)
                    KAHAN_ADD(acc[r][cq], cmp[r][cq], tmp[r][cq]);
        }
        __syncthreads();
    }

    // ---- final scalar input column (x_t for enc, dec_in for dec) ----
    int jb = jc + tx * 4;
    float4 wlast = *(const float4*)&W[KMAIN * G4 + jb];
    #pragma unroll
    for (int r = 0; r < 2; r++) {
        int b = rb + ty * 2 + r;
        float e = is_enc ? xptr[b * S + t] : g_ext[b * 257 + 256];
        KAHAN_ADD(acc[r][0], cmp[r][0], e * wlast.x);
        KAHAN_ADD(acc[r][1], cmp[r][1], e * wlast.y);
        KAHAN_ADD(acc[r][2], cmp[r][2], e * wlast.z);
        KAHAN_ADD(acc[r][3], cmp[r][3], e * wlast.w);
    }

    int unit = (jc >> 2) + tx;              // hidden unit index 0..255
    float bi = bias[jb + 0], bf = bias[jb + 1], bg = bias[jb + 2], bo = bias[jb + 3];
    #pragma unroll
    for (int r = 0; r < 2; r++) {
        int b = rb + ty * 2 + r;
        float iv = sig_p(acc[r][0] + bi);
        float fv = sig_p(acc[r][1] + bf);
        float gv = tanh_p(acc[r][2] + bg);
        float ov = sig_p(acc[r][3] + bo);
        float cold = g_c[b * H + unit];
        float cn = fv * cold + iv * gv;
        float hh = ov * tanh_p(cn);
        g_c[b * H + unit] = cn;
        h_out[b * H + unit] = hh;
        if (is_enc) g_enc_out[b * (S * H) + t * H + unit] = hh;
    }
}

// ---------------- encW1 precompute: [b][u][s] = enc_out[b,s,:] . W1[u,:] ----
__global__ __launch_bounds__(256) void encW1_kernel(const float* __restrict__ W1)
{
    int w = blockIdx.x * 8 + (threadIdx.x >> 5);
    int lane = threadIdx.x & 31;
    int b = w >> 8, s = w & 255;
    const float* e = g_enc_out + b * (S * H) + s * H;
    float ev[8];
    #pragma unroll
    for (int i = 0; i < 8; i++) ev[i] = e[lane + 32 * i];
    #pragma unroll
    for (int u = 0; u < U; u++) {
        float p = 0.f, c = 0.f;
        #pragma unroll
        for (int i = 0; i < 8; i++) KAHAN_ADD(p, c, ev[i] * W1[u * 256 + lane + 32 * i]);
        #pragma unroll
        for (int o = 16; o; o >>= 1) p += __shfl_xor_sync(0xffffffffu, p, o);
        if (lane == 0) g_encW1[b * (U * S) + u * S + s] = p;
    }
}

// ---------------- fused attention step: logits/softmax/argmax/loss/di ------
__global__ __launch_bounds__(256) void attn_step(const float* __restrict__ x,
                                                 const void* __restrict__ yv,
                                                 const float* __restrict__ W2,
                                                 const float* __restrict__ V,
                                                 float* __restrict__ outp,
                                                 int t, int parity)
{
    const float* h_in = parity ? g_hB : g_hA;
    int b = blockIdx.x, tid = threadIdx.x;

    __shared__ float sh_h[256];
    __shared__ float sh_w2h[16];
    __shared__ float sV[16];
    __shared__ float sh_log[256];
    __shared__ float sh_aj[256];
    __shared__ float sh_red[256];
    __shared__ int   sh_idx[256];

    sh_h[tid] = h_in[b * H + tid];
    if (tid == 0) g_ext[b * 257 + 256] = g_decnext[b];   // dec_in for THIS step
    if (tid < U)  sV[tid] = V[tid];
    __syncthreads();

    int wid = tid >> 5, lane = tid & 31;
    for (int u = wid; u < U; u += 8) {
        float p = 0.f, c = 0.f;
        #pragma unroll
        for (int k = lane; k < 256; k += 32) KAHAN_ADD(p, c, sh_h[k] * W2[u * 256 + k]);
        #pragma unroll
        for (int o = 16; o; o >>= 1) p += __shfl_xor_sync(0xffffffffu, p, o);
        if (lane == 0) sh_w2h[u] = p;
    }
    __syncthreads();

    const float* ew = g_encW1 + b * (U * S) + tid;
    float lg = 0.f, lgc = 0.f;
    #pragma unroll
    for (int u = 0; u < U; u++)
        KAHAN_ADD(lg, lgc, sV[u] * tanh_p(ew[u * S] + sh_w2h[u]));
    sh_log[tid] = lg;
    sh_red[tid] = lg;
    sh_idx[tid] = tid;
    __syncthreads();

    // argmax (first occurrence on ties, matching jnp.argmax)
    #pragma unroll
    for (int off = 128; off; off >>= 1) {
        if (tid < off) {
            float ov = sh_red[tid + off]; int oi = sh_idx[tid + off];
            float cv = sh_red[tid];       int ci = sh_idx[tid];
            if (ov > cv || (ov == cv && oi < ci)) { sh_red[tid] = ov; sh_idx[tid] = oi; }
        }
        __syncthreads();
    }
    float mx = sh_red[0]; int mi = sh_idx[0];
    __syncthreads();

    float p = exp_p(lg - mx);
    sh_red[tid] = p;
    __syncthreads();
    #pragma unroll
    for (int off = 128; off; off >>= 1) {
        if (tid < off) sh_red[tid] += sh_red[tid + off];
        __syncthreads();
    }
    float sum = sh_red[0];
    sh_aj[tid] = __fdiv_rn(p, sum);

    if (tid == 0) {
        int yi = g_y64 ? (int)((const long long*)yv)[b * S + t]
                       : ((const int*)yv)[b * S + t];
        float logpy = sh_log[yi] - mx - (float)log((double)sum);
        g_lossbuf[t * B + b] = -logpy;
        outp[t * B + b] = (float)mi;
        g_decnext[b] = x[b * S + yi];    // teacher force for NEXT step
    }
    __syncthreads();

    // di[b][tid] = sum_s aj[s] * enc_out[b][s][tid]   (feeds the recurrence)
    // chunk-8 FFMA + Kahan fold: short serial chain, deep load MLP
    const float* eb = g_enc_out + b * (S * H) + tid;
    float acc = 0.f, accc = 0.f;
    #pragma unroll 4
    for (int c8 = 0; c8 < 32; c8++) {
        float tmp = 0.f;
        #pragma unroll
        for (int kk = 0; kk < 8; kk++) {
            int s2 = c8 * 8 + kk;
            tmp = fmaf(sh_aj[s2], eb[s2 * H], tmp);
        }
        KAHAN_ADD(acc, accc, tmp);
    }
    g_ext[b * 257 + tid] = acc;
}

// ---------------- deterministic loss reduction ------------------------------
__global__ void loss_reduce(float* __restrict__ outp, int do_write)
{
    __shared__ float sr[256];
    int tid = threadIdx.x;
    float a = 0.f, c = 0.f;
    for (int i = tid; i < S * B; i += 256) KAHAN_ADD(a, c, g_lossbuf[i]);
    sr[tid] = a;
    __syncthreads();
    #pragma unroll
    for (int off = 128; off; off >>= 1) {
        if (tid < off) sr[tid] += sr[tid + off];
        __syncthreads();
    }
    if (tid == 0 && do_write) outp[S * B] = __fdiv_rn(sr[0], 512.f * 512.f);
}

// ---------------- host launch ----------------------------------------------
extern "C" void kernel_launch(void* const* d_in, const int* in_sizes, int n_in,
                              void* d_out, int out_size)
{
    const float* x    = (const float*)d_in[0];
    const void*  y    = d_in[1];
    const float* eWih = (const float*)d_in[2];
    const float* eWhh = (const float*)d_in[3];
    const float* ebih = (const float*)d_in[4];
    const float* ebhh = (const float*)d_in[5];
    const float* dWih = (const float*)d_in[6];
    const float* dWhh = (const float*)d_in[7];
    const float* dbih = (const float*)d_in[8];
    const float* dbhh = (const float*)d_in[9];
    const float* W1   = (const float*)d_in[10];
    const float* W2   = (const float*)d_in[11];
    const float* V    = (const float*)d_in[12];
    float* outp = (float*)d_out;

    prep_kernel<<<(513 * G4 + 255) / 256, 256>>>(eWih, eWhh, ebih, ebhh,
                                                 dWih, dWhh, dbih, dbhh);
    init_kernel<<<(B * H + 255) / 256, 256>>>();
    detect_y<<<1, 1>>>(y);

    dim3 grid(G4 / 64, B / 64);   // 16 x 8

    // encoder (KMAIN=256, x_t handled in epilogue)
    for (int t = 0; t < S; t++)
        lstm_step<<<grid, 512>>>(x, 256, 1, t, t & 1);

    encW1_kernel<<<B * S / 8, 256>>>(W1);

    // decoder (KMAIN=512, dec_in handled in epilogue)
    for (int t = 0; t < S; t++) {
        attn_step<<<B, 256>>>(x, y, W2, V, outp, t, t & 1);
        lstm_step<<<grid, 512>>>(x, 512, 0, t, t & 1);
    }

    loss_reduce<<<1, 256>>>(outp, out_size > S * B ? 1 : 0);
}